// round 15
// baseline (speedup 1.0000x reference)
#include <cuda_runtime.h>
#include <cuda_fp16.h>
#include <cstdint>

// ---------------------------------------------------------------------------
// Radon transform, 180 angles, 512x512, batch 2 — round 15.
//
// Base = R14 (80.5us wall; fp16 corner cells, magic floor, head/body/tail).
// Single change: coordinate math packed into f32x2 ops on (x,y) lanes:
//   rfi2   += (4,4)                      (add.rn.f32x2)
//   pxy     = rfi2*(dxs,dys)+(xc0,yc0)   (fma.rn.f32x2)
//   pb2     = pxy + (2^23,2^23)          (add.RZ.f32x2)  <- magic floor
//   pbm     = pb2 + (-2^23,-2^23)        (add.rn.f32x2)
//   frac2   = pbm*(-1,-1) + pxy          (fma.rn.f32x2 == pxy - pbm, 1 rounding)
// 9 scalar instr -> 5 packed. Per-lane math is bit-identical to R14:
// rel_err must stay EXACTLY 4.700945e-4.
// ---------------------------------------------------------------------------

#define W    512
#define NT   180
#define PW   520                 // cells per row; 520*16B multiple of 128B
#define PH   520
#define NPIX (PW * PH)
#define PAD  4
#define MAGIC 8388608.0f         // 2^23
#define KBIAS (0x4B000000u * (unsigned)(PW + 1))   // mod-2^32 wrap is intended

__device__ uint4 g_padA[NPIX];   // normal orientation  (16B corner cells)
__device__ uint4 g_padB[NPIX];   // transposed orientation

typedef unsigned long long u64;

__device__ __forceinline__ u64 pk2(float lo, float hi) {
    u64 r; asm("mov.b64 %0, {%1, %2};" : "=l"(r) : "f"(lo), "f"(hi)); return r;
}
__device__ __forceinline__ void unpk2(u64 v, float& lo, float& hi) {
    asm("mov.b64 {%0, %1}, %2;" : "=f"(lo), "=f"(hi) : "l"(v));
}
__device__ __forceinline__ u64 ffma2(u64 a, u64 b, u64 c) {
    u64 d; asm("fma.rn.f32x2 %0, %1, %2, %3;" : "=l"(d) : "l"(a), "l"(b), "l"(c)); return d;
}
__device__ __forceinline__ u64 fadd2(u64 a, u64 b) {
    u64 d; asm("add.rn.f32x2 %0, %1, %2;" : "=l"(d) : "l"(a), "l"(b)); return d;
}
__device__ __forceinline__ u64 fadd2_rz(u64 a, u64 b) {
    u64 d; asm("add.rz.f32x2 %0, %1, %2;" : "=l"(d) : "l"(a), "l"(b)); return d;
}
__device__ __forceinline__ u64 h2f2(__half2 h) {         // half2 -> packed f32x2
    float2 f = __half22float2(h);
    return pk2(f.x, f.y);
}

// ---- fused build: z=0 -> padA (direct, coalesced), z=1 -> padB (transpose) --
__global__ __launch_bounds__(256) void build_pads(const float* __restrict__ x) {
    __shared__ float s[2][33][35];
    int tid = threadIdx.x;

    if (blockIdx.z == 0) {
        int idx = blockIdx.x * 256 + tid;
        if (idx >= NPIX) return;
        int ky = idx / PW;
        int kx = idx - ky * PW;
        int y  = ky - PAD;
        int x0 = kx - PAD;

        auto val = [&](int b, int r, int c) -> float {
            if ((unsigned)r < W && (unsigned)c < W)
                return x[b * (W * W) + r * W + c];
            return 0.0f;
        };
        __half2 h00 = __floats2half2_rn(val(0, y,     x0),     val(1, y,     x0));
        __half2 h01 = __floats2half2_rn(val(0, y,     x0 + 1), val(1, y,     x0 + 1));
        __half2 h10 = __floats2half2_rn(val(0, y + 1, x0),     val(1, y + 1, x0));
        __half2 h11 = __floats2half2_rn(val(0, y + 1, x0 + 1), val(1, y + 1, x0 + 1));
        uint4 cell;
        cell.x = *reinterpret_cast<uint32_t*>(&h00);
        cell.y = *reinterpret_cast<uint32_t*>(&h01);
        cell.z = *reinterpret_cast<uint32_t*>(&h10);
        cell.w = *reinterpret_cast<uint32_t*>(&h11);
        g_padA[idx] = cell;
    } else {
        const int TILES = (PW + 31) / 32;            // 17
        if (blockIdx.x >= TILES * TILES) return;
        int TX = (blockIdx.x % TILES) * 32;          // kx tile base (orig rows)
        int TY = (blockIdx.x / TILES) * 32;          // ky tile base (orig cols)
        int lane = tid & 31;
        int ty   = tid >> 5;

        for (int rr = ty; rr < 33; rr += 8) {
            int orow = TX - PAD + rr;
            for (int cc = lane; cc < 33; cc += 32) {
                int ocol = TY - PAD + cc;
                float v0 = 0.f, v1 = 0.f;
                if ((unsigned)orow < W && (unsigned)ocol < W) {
                    v0 = x[orow * W + ocol];
                    v1 = x[W * W + orow * W + ocol];
                }
                s[0][rr][cc] = v0;
                s[1][rr][cc] = v1;
            }
        }
        __syncthreads();

        int kx = TX + lane;
        if (kx >= PW) return;
        for (int j = ty; j < 32; j += 8) {
            int ky = TY + j;
            if (ky >= PH) continue;
            __half2 h00 = __floats2half2_rn(s[0][lane][j],         s[1][lane][j]);
            __half2 h01 = __floats2half2_rn(s[0][lane + 1][j],     s[1][lane + 1][j]);
            __half2 h10 = __floats2half2_rn(s[0][lane][j + 1],     s[1][lane][j + 1]);
            __half2 h11 = __floats2half2_rn(s[0][lane + 1][j + 1], s[1][lane + 1][j + 1]);
            uint4 cell;
            cell.x = *reinterpret_cast<uint32_t*>(&h00);
            cell.y = *reinterpret_cast<uint32_t*>(&h01);
            cell.z = *reinterpret_cast<uint32_t*>(&h10);
            cell.w = *reinterpret_cast<uint32_t*>(&h11);
            g_padB[ky * PW + kx] = cell;
        }
    }
}

// ---- main kernel: 128 threads = 32 columns x 4 r-phases ---------------------
__global__ __launch_bounds__(128) void radon_kernel(float* __restrict__ out) {
    __shared__ float2 red[4][32];

    int tid  = threadIdx.x;
    int lane = tid & 31;
    int wid  = tid >> 5;
    int t    = blockIdx.y;

    float th = (float)t * 0.017453292519943295f;
    float s  = sinf(th);                         // >= 0 for t in [0,180)
    float ct = cosf(th);
    float act = fabsf(ct);

    // shape + orientation selection (uniform per block)
    float bestc = 1e30f; int best_lw = 5; int best_tr = 0;
#pragma unroll
    for (int o = 0; o < 2; o++) {
        float a  = o ? act : s;
        float b  = o ? s   : act;
        float cx = o ? s   : act;
#pragma unroll
        for (int lw = 3; lw <= 5; lw++) {
            float wf = (float)(1 << lw);
            float hf = 32.0f / wf;
            float cost = (wf * a + hf * b + 2.0f) * (1.0f + wf * cx * (1.0f / 16.0f));
            if (cost < bestc) { bestc = cost; best_lw = lw; best_tr = o; }
        }
    }
    int lw     = best_lw;
    int w_     = 1 << lw;
    int h_     = 32 >> lw;
    int cgbits = 5 - lw;
    int cl  = lane & (w_ - 1);
    int rp  = lane >> lw;
    int col_group   = wid & ((1 << cgbits) - 1);
    int phase_group = wid >> cgbits;
    int phase   = phase_group * h_ + rp;         // 0..3
    int c_local = col_group * w_ + cl;           // 0..31
    int c = blockIdx.x * 32 + c_local;

    float base_c = (float)(2 * c + 1) * (1.0f / 512.0f) - 1.0f;
    float ix0 = fmaf(-255.5f, s,  fmaf( 256.0f * ct, base_c, 255.5f));
    float iy0 = fmaf(-255.5f, ct, fmaf(-256.0f * s,  base_c, 255.5f));

    // clip r to where (ix,iy) in [-1,512]^2
    float sx  = fmaxf(s, 1e-8f);
    float sy  = (act < 1e-8f) ? ((ct < 0.f) ? -1e-8f : 1e-8f) : ct;
    float ivx = 1.0f / sx;
    float ivy = 1.0f / sy;
    float tx1 = (-1.0f  - ix0) * ivx;
    float tx2 = (512.0f - ix0) * ivx;
    float ty1 = (-1.0f  - iy0) * ivy;
    float ty2 = (512.0f - iy0) * ivy;
    float rminf = fmaxf(fmaxf(fminf(tx1, tx2), fminf(ty1, ty2)), 0.0f);
    float rmaxf = fminf(fminf(fmaxf(tx1, tx2), fmaxf(ty1, ty2)), 511.0f);
    int ra = (int)floorf(rminf);
    int rb = (int)ceilf(rmaxf);

    int ra_w  = __reduce_min_sync(0xffffffffu, ra);   // warp outer bounds
    int rb_w  = __reduce_max_sync(0xffffffffu, rb);
    int ra_hi = __reduce_max_sync(0xffffffffu, ra);   // interior (all-lanes-valid)
    int rb_lo = __reduce_min_sync(0xffffffffu, rb);
    float ra1f = (float)(ra - 1);        // samples at ra-1 / rb+1 are EXACTLY 0
    float rb1f = (float)(rb + 1);

    float xc0, yc0, dxs, dys;
    const uint4* __restrict__ base;
    if (!best_tr) { xc0 = ix0 + (float)PAD; dxs = s;  yc0 = iy0 + (float)PAD; dys = ct; base = g_padA; }
    else          { xc0 = iy0 + (float)PAD; dxs = ct; yc0 = ix0 + (float)PAD; dys = s;  base = g_padB; }

    const u64 D2   = pk2(dxs, dys);      // packed (dx/dr, dy/dr)
    const u64 XC2  = pk2(xc0, yc0);      // packed origin
    const u64 MG2  = pk2(MAGIC, MAGIC);
    const u64 NMG2 = pk2(-MAGIC, -MAGIC);
    const u64 M1_2 = pk2(-1.0f, -1.0f);
    const u64 F4_2 = pk2(4.0f, 4.0f);

    u64 acc0 = pk2(0.0f, 0.0f);
    u64 acc1 = pk2(0.0f, 0.0f);
    int toggle = 0;

    auto do_sample = [&](u64 rr2) {
        u64 pxy = ffma2(rr2, D2, XC2);               // (px, py)
        u64 pb2 = fadd2_rz(pxy, MG2);                // bits = 0x4B000000 + floor
        u64 pbm = fadd2(pb2, NMG2);                  // (floor(px), floor(py))
        u64 fr2 = ffma2(pbm, M1_2, pxy);             // exact fractions (== pxy-pbm)

        float pbxf, pbyf, fx, fy;
        unpk2(pb2, pbxf, pbyf);                      // register-pair access
        unpk2(fr2, fx, fy);
        uint32_t idx = __float_as_uint(pbyf) * (unsigned)PW
                     + __float_as_uint(pbxf) - KBIAS; // = y0*PW + x0 (mod 2^32)

        uint4 cell = __ldg(base + idx);              // ONE LDG.128: all 4 corners

        __half2 v00 = *reinterpret_cast<__half2*>(&cell.x);
        __half2 v01 = *reinterpret_cast<__half2*>(&cell.y);
        __half2 v10 = *reinterpret_cast<__half2*>(&cell.z);
        __half2 v11 = *reinterpret_cast<__half2*>(&cell.w);

        __half2 fxh = __floats2half2_rn(fx, fx);
        __half2 fyh = __floats2half2_rn(fy, fy);
        __half2 l0h = __hfma2(fxh, __hsub2(v01, v00), v00);  // x-lerp row y0
        __half2 l1h = __hfma2(fxh, __hsub2(v11, v10), v10);  // x-lerp row y0+1
        __half2 vvh = __hfma2(fyh, __hsub2(l1h, l0h), l0h);  // y-lerp

        u64 vv = h2f2(vvh);
        if (toggle) acc1 = fadd2(acc1, vv); else acc0 = fadd2(acc0, vv);
        toggle ^= 1;
    };

    int   r   = ra_w + phase;
    float rfi = (float)r;                // exact float shadow of the counter
    u64   rfi2 = pk2(rfi, rfi);

    // HEAD: some lanes below their own range -> clamp to zero cells
    for (; r < ra_hi; r += 4, rfi += 4.0f) {
        float rfc = fminf(fmaxf(rfi, ra1f), rb1f);
        do_sample(pk2(rfc, rfc));
    }
    rfi2 = pk2(rfi, rfi);

    // BODY: every lane in-range -> no clamp (bit-identical: clamp was no-op)
#pragma unroll 8
    for (; r <= rb_lo; r += 4, rfi2 = fadd2(rfi2, F4_2))
        do_sample(rfi2);
    rfi = (float)r;

    // TAIL: some lanes past their own range -> clamp to zero cells
    for (; r <= rb_w; r += 4, rfi += 4.0f) {
        float rfc = fminf(fmaxf(rfi, ra1f), rb1f);
        do_sample(pk2(rfc, rfc));
    }

    u64 acc = fadd2(acc0, acc1);

    float a0, a1;
    unpk2(acc, a0, a1);
    red[phase][c_local] = make_float2(a0, a1);
    __syncthreads();

    if (tid < 32) {
        float2 r0 = red[0][tid], r1 = red[1][tid], r2 = red[2][tid], r3 = red[3][tid];
        float sa = (r0.x + r1.x) + (r2.x + r3.x);
        float sb = (r0.y + r1.y) + (r2.y + r3.y);
        const float inv = 1.0f / 512.0f;
        int c2 = blockIdx.x * 32 + tid;
        int o0 = c2 * NT + t;
        out[o0]           = sa * inv;            // batch 0
        out[W * NT + o0]  = sb * inv;            // batch 1
    }
}

extern "C" void kernel_launch(void* const* d_in, const int* in_sizes, int n_in,
                              void* d_out, int out_size) {
    const float* x = (const float*)d_in[0];
    float* out = (float*)d_out;

    dim3 bgrid((NPIX + 255) / 256, 1, 2);        // z=0: padA, z=1: padB
    build_pads<<<bgrid, 256>>>(x);

    dim3 grid(W / 32, NT);
    radon_kernel<<<grid, 128>>>(out);
}

// round 16
// speedup vs baseline: 1.0246x; 1.0246x over previous
#include <cuda_runtime.h>
#include <cuda_fp16.h>
#include <cstdint>

// ---------------------------------------------------------------------------
// Radon transform, 180 angles, 512x512, batch 2 — round 16.
//
// History: R12 (single always-clamped loop) had the best radon (78.7us,
// regs 29); R14's head/body/tail split hurt (+11 regs, loop overhead); R15's
// packed-f32x2 coords were bit-exact and cut regs. R16 combines the winners:
// R12 structure + R15 packed coordinate chain. All per-lane math identical
// to R12 -> rel_err must stay EXACTLY 4.700945e-4.
// ---------------------------------------------------------------------------

#define W    512
#define NT   180
#define PW   520                 // cells per row; 520*16B multiple of 128B
#define PH   520
#define NPIX (PW * PH)
#define PAD  4
#define MAGIC 8388608.0f         // 2^23
#define KBIAS (0x4B000000u * (unsigned)(PW + 1))   // mod-2^32 wrap is intended

__device__ uint4 g_padA[NPIX];   // normal orientation  (16B corner cells)
__device__ uint4 g_padB[NPIX];   // transposed orientation

typedef unsigned long long u64;

__device__ __forceinline__ u64 pk2(float lo, float hi) {
    u64 r; asm("mov.b64 %0, {%1, %2};" : "=l"(r) : "f"(lo), "f"(hi)); return r;
}
__device__ __forceinline__ void unpk2(u64 v, float& lo, float& hi) {
    asm("mov.b64 {%0, %1}, %2;" : "=f"(lo), "=f"(hi) : "l"(v));
}
__device__ __forceinline__ u64 ffma2(u64 a, u64 b, u64 c) {
    u64 d; asm("fma.rn.f32x2 %0, %1, %2, %3;" : "=l"(d) : "l"(a), "l"(b), "l"(c)); return d;
}
__device__ __forceinline__ u64 fadd2(u64 a, u64 b) {
    u64 d; asm("add.rn.f32x2 %0, %1, %2;" : "=l"(d) : "l"(a), "l"(b)); return d;
}
__device__ __forceinline__ u64 fadd2_rz(u64 a, u64 b) {
    u64 d; asm("add.rz.f32x2 %0, %1, %2;" : "=l"(d) : "l"(a), "l"(b)); return d;
}
__device__ __forceinline__ u64 h2f2(__half2 h) {         // half2 -> packed f32x2
    float2 f = __half22float2(h);
    return pk2(f.x, f.y);
}

// ---- fused build: z=0 -> padA (direct, coalesced), z=1 -> padB (transpose) --
__global__ __launch_bounds__(256) void build_pads(const float* __restrict__ x) {
    __shared__ float s[2][33][35];
    int tid = threadIdx.x;

    if (blockIdx.z == 0) {
        int idx = blockIdx.x * 256 + tid;
        if (idx >= NPIX) return;
        int ky = idx / PW;
        int kx = idx - ky * PW;
        int y  = ky - PAD;
        int x0 = kx - PAD;

        auto val = [&](int b, int r, int c) -> float {
            if ((unsigned)r < W && (unsigned)c < W)
                return x[b * (W * W) + r * W + c];
            return 0.0f;
        };
        __half2 h00 = __floats2half2_rn(val(0, y,     x0),     val(1, y,     x0));
        __half2 h01 = __floats2half2_rn(val(0, y,     x0 + 1), val(1, y,     x0 + 1));
        __half2 h10 = __floats2half2_rn(val(0, y + 1, x0),     val(1, y + 1, x0));
        __half2 h11 = __floats2half2_rn(val(0, y + 1, x0 + 1), val(1, y + 1, x0 + 1));
        uint4 cell;
        cell.x = *reinterpret_cast<uint32_t*>(&h00);
        cell.y = *reinterpret_cast<uint32_t*>(&h01);
        cell.z = *reinterpret_cast<uint32_t*>(&h10);
        cell.w = *reinterpret_cast<uint32_t*>(&h11);
        g_padA[idx] = cell;
    } else {
        const int TILES = (PW + 31) / 32;            // 17
        if (blockIdx.x >= TILES * TILES) return;
        int TX = (blockIdx.x % TILES) * 32;          // kx tile base (orig rows)
        int TY = (blockIdx.x / TILES) * 32;          // ky tile base (orig cols)
        int lane = tid & 31;
        int ty   = tid >> 5;

        for (int rr = ty; rr < 33; rr += 8) {
            int orow = TX - PAD + rr;
            for (int cc = lane; cc < 33; cc += 32) {
                int ocol = TY - PAD + cc;
                float v0 = 0.f, v1 = 0.f;
                if ((unsigned)orow < W && (unsigned)ocol < W) {
                    v0 = x[orow * W + ocol];
                    v1 = x[W * W + orow * W + ocol];
                }
                s[0][rr][cc] = v0;
                s[1][rr][cc] = v1;
            }
        }
        __syncthreads();

        int kx = TX + lane;
        if (kx >= PW) return;
        for (int j = ty; j < 32; j += 8) {
            int ky = TY + j;
            if (ky >= PH) continue;
            __half2 h00 = __floats2half2_rn(s[0][lane][j],         s[1][lane][j]);
            __half2 h01 = __floats2half2_rn(s[0][lane + 1][j],     s[1][lane + 1][j]);
            __half2 h10 = __floats2half2_rn(s[0][lane][j + 1],     s[1][lane][j + 1]);
            __half2 h11 = __floats2half2_rn(s[0][lane + 1][j + 1], s[1][lane + 1][j + 1]);
            uint4 cell;
            cell.x = *reinterpret_cast<uint32_t*>(&h00);
            cell.y = *reinterpret_cast<uint32_t*>(&h01);
            cell.z = *reinterpret_cast<uint32_t*>(&h10);
            cell.w = *reinterpret_cast<uint32_t*>(&h11);
            g_padB[ky * PW + kx] = cell;
        }
    }
}

// ---- main kernel: 128 threads = 32 columns x 4 r-phases ---------------------
__global__ __launch_bounds__(128) void radon_kernel(float* __restrict__ out) {
    __shared__ float2 red[4][32];

    int tid  = threadIdx.x;
    int lane = tid & 31;
    int wid  = tid >> 5;
    int t    = blockIdx.y;

    float th = (float)t * 0.017453292519943295f;
    float s  = sinf(th);                         // >= 0 for t in [0,180)
    float ct = cosf(th);
    float act = fabsf(ct);

    // shape + orientation selection (uniform per block)
    float bestc = 1e30f; int best_lw = 5; int best_tr = 0;
#pragma unroll
    for (int o = 0; o < 2; o++) {
        float a  = o ? act : s;
        float b  = o ? s   : act;
        float cx = o ? s   : act;
#pragma unroll
        for (int lw = 3; lw <= 5; lw++) {
            float wf = (float)(1 << lw);
            float hf = 32.0f / wf;
            float cost = (wf * a + hf * b + 2.0f) * (1.0f + wf * cx * (1.0f / 16.0f));
            if (cost < bestc) { bestc = cost; best_lw = lw; best_tr = o; }
        }
    }
    int lw     = best_lw;
    int w_     = 1 << lw;
    int h_     = 32 >> lw;
    int cgbits = 5 - lw;
    int cl  = lane & (w_ - 1);
    int rp  = lane >> lw;
    int col_group   = wid & ((1 << cgbits) - 1);
    int phase_group = wid >> cgbits;
    int phase   = phase_group * h_ + rp;         // 0..3
    int c_local = col_group * w_ + cl;           // 0..31
    int c = blockIdx.x * 32 + c_local;

    float base_c = (float)(2 * c + 1) * (1.0f / 512.0f) - 1.0f;
    float ix0 = fmaf(-255.5f, s,  fmaf( 256.0f * ct, base_c, 255.5f));
    float iy0 = fmaf(-255.5f, ct, fmaf(-256.0f * s,  base_c, 255.5f));

    // clip r to where (ix,iy) in [-1,512]^2
    float sx  = fmaxf(s, 1e-8f);
    float sy  = (act < 1e-8f) ? ((ct < 0.f) ? -1e-8f : 1e-8f) : ct;
    float ivx = 1.0f / sx;
    float ivy = 1.0f / sy;
    float tx1 = (-1.0f  - ix0) * ivx;
    float tx2 = (512.0f - ix0) * ivx;
    float ty1 = (-1.0f  - iy0) * ivy;
    float ty2 = (512.0f - iy0) * ivy;
    float rminf = fmaxf(fmaxf(fminf(tx1, tx2), fminf(ty1, ty2)), 0.0f);
    float rmaxf = fminf(fminf(fmaxf(tx1, tx2), fmaxf(ty1, ty2)), 511.0f);
    int ra = (int)floorf(rminf);
    int rb = (int)ceilf(rmaxf);

    int ra_w = __reduce_min_sync(0xffffffffu, ra);   // warp-uniform bounds
    int rb_w = __reduce_max_sync(0xffffffffu, rb);
    float ra1f = (float)(ra - 1);        // samples at ra-1 / rb+1 are EXACTLY 0
    float rb1f = (float)(rb + 1);

    float xc0, yc0, dxs, dys;
    const uint4* __restrict__ base;
    if (!best_tr) { xc0 = ix0 + (float)PAD; dxs = s;  yc0 = iy0 + (float)PAD; dys = ct; base = g_padA; }
    else          { xc0 = iy0 + (float)PAD; dxs = ct; yc0 = ix0 + (float)PAD; dys = s;  base = g_padB; }

    const u64 D2   = pk2(dxs, dys);      // packed (dx/dr, dy/dr)
    const u64 XC2  = pk2(xc0, yc0);      // packed origin
    const u64 MG2  = pk2(MAGIC, MAGIC);
    const u64 NMG2 = pk2(-MAGIC, -MAGIC);
    const u64 M1_2 = pk2(-1.0f, -1.0f);

    u64 acc0 = pk2(0.0f, 0.0f);
    u64 acc1 = pk2(0.0f, 0.0f);
    int toggle = 0;

    float rfi = (float)(ra_w + phase);   // exact float shadow of the counter
#pragma unroll 8
    for (int r = ra_w + phase; r <= rb_w; r += 4, rfi += 4.0f) {
        float rfc = fminf(fmaxf(rfi, ra1f), rb1f);   // per-lane clamp (zero cells)
        u64 rr2 = pk2(rfc, rfc);

        u64 pxy = ffma2(rr2, D2, XC2);               // (px, py)
        u64 pb2 = fadd2_rz(pxy, MG2);                // bits = 0x4B000000 + floor
        u64 pbm = fadd2(pb2, NMG2);                  // (floor(px), floor(py))
        u64 fr2 = ffma2(pbm, M1_2, pxy);             // exact fractions (== pxy-pbm)

        float pbxf, pbyf, fx, fy;
        unpk2(pb2, pbxf, pbyf);                      // register-pair access
        unpk2(fr2, fx, fy);
        uint32_t idx = __float_as_uint(pbyf) * (unsigned)PW
                     + __float_as_uint(pbxf) - KBIAS; // = y0*PW + x0 (mod 2^32)

        uint4 cell = __ldg(base + idx);              // ONE LDG.128: all 4 corners

        __half2 v00 = *reinterpret_cast<__half2*>(&cell.x);
        __half2 v01 = *reinterpret_cast<__half2*>(&cell.y);
        __half2 v10 = *reinterpret_cast<__half2*>(&cell.z);
        __half2 v11 = *reinterpret_cast<__half2*>(&cell.w);

        __half2 fxh = __floats2half2_rn(fx, fx);
        __half2 fyh = __floats2half2_rn(fy, fy);
        __half2 l0h = __hfma2(fxh, __hsub2(v01, v00), v00);  // x-lerp row y0
        __half2 l1h = __hfma2(fxh, __hsub2(v11, v10), v10);  // x-lerp row y0+1
        __half2 vvh = __hfma2(fyh, __hsub2(l1h, l0h), l0h);  // y-lerp

        u64 vv = h2f2(vvh);
        if (toggle) acc1 = fadd2(acc1, vv); else acc0 = fadd2(acc0, vv);
        toggle ^= 1;
    }
    u64 acc = fadd2(acc0, acc1);

    float a0, a1;
    unpk2(acc, a0, a1);
    red[phase][c_local] = make_float2(a0, a1);
    __syncthreads();

    if (tid < 32) {
        float2 r0 = red[0][tid], r1 = red[1][tid], r2 = red[2][tid], r3 = red[3][tid];
        float sa = (r0.x + r1.x) + (r2.x + r3.x);
        float sb = (r0.y + r1.y) + (r2.y + r3.y);
        const float inv = 1.0f / 512.0f;
        int c2 = blockIdx.x * 32 + tid;
        int o0 = c2 * NT + t;
        out[o0]           = sa * inv;            // batch 0
        out[W * NT + o0]  = sb * inv;            // batch 1
    }
}

extern "C" void kernel_launch(void* const* d_in, const int* in_sizes, int n_in,
                              void* d_out, int out_size) {
    const float* x = (const float*)d_in[0];
    float* out = (float*)d_out;

    dim3 bgrid((NPIX + 255) / 256, 1, 2);        // z=0: padA, z=1: padB
    build_pads<<<bgrid, 256>>>(x);

    dim3 grid(W / 32, NT);
    radon_kernel<<<grid, 128>>>(out);
}